// round 14
// baseline (speedup 1.0000x reference)
#include <cuda_runtime.h>
#include <cuda_bf16.h>

#define G_SIZE 4096
#define B_SIZE 16
#define NCH 15
#define D_MAX 20          // Taylor degree: terms d = 0..20
#define ND (D_MAX + 1)    // 21
#define NSPL 32
#define LPER (G_SIZE / NSPL)   // 128

// Split-innermost layout: Mo_part[((c*ND + d)*B_SIZE + b)*NSPL + sp]  (645 KB)
__device__ float Mo_part[NCH * ND * B_SIZE * NSPL];

#define LOG2E 1.4426950408889634f

__device__ __forceinline__ float ex2f(float x) {
    float r; asm("ex2.approx.ftz.f32 %0, %1;" : "=f"(r) : "f"(x)); return r;
}

// Moments, register-resident: one CTA = (sp, c) computes ALL 21 degrees.
// 512 threads = 16 warps, b = wid. Lane owns 4 l's (one float4 slice of the sp-chunk).
// acc[d] = sum over lane's 4 l of density*gw*exp(-gl^2 xi)*gl^d, built by power chains.
__global__ __launch_bounds__(512) void moments_kernel(const float* __restrict__ xi,
                                                      const float* __restrict__ grid,
                                                      const float* __restrict__ gw,
                                                      const float* __restrict__ density) {
    const int sp = blockIdx.x;      // 0..31
    const int c  = blockIdx.y;      // 0..14
    const int tid = threadIdx.x;
    const int wid = tid >> 5, lane = tid & 31;
    const int b = wid;
    const int fidx = sp * (LPER / 4) + lane;   // float4 index into 4096-float arrays

    float4 g4 = ((const float4*)grid)[fidx];
    float4 w4 = ((const float4*)gw)[fidx];
    float4 d4 = ((const float4*)(density + b * G_SIZE))[fidx];

    const float xi_t = 1.0f + ex2f(-xi[c] * LOG2E);
    const float cg = -xi_t * LOG2E;

    // p_j = density_j * gw_j * exp(-g_j^2 * xi_t); then iterate p_j *= g_j
    float p0 = d4.x * w4.x * ex2f(g4.x * g4.x * cg);
    float p1 = d4.y * w4.y * ex2f(g4.y * g4.y * cg);
    float p2 = d4.z * w4.z * ex2f(g4.z * g4.z * cg);
    float p3 = d4.w * w4.w * ex2f(g4.w * g4.w * cg);

    float acc[ND];
    acc[0] = (p0 + p1) + (p2 + p3);
#pragma unroll
    for (int d = 1; d < ND; ++d) {
        p0 *= g4.x; p1 *= g4.y; p2 *= g4.z; p3 *= g4.w;
        acc[d] = (p0 + p1) + (p2 + p3);
    }

    // Warp reduce all 21 degrees
#pragma unroll
    for (int d = 0; d < ND; ++d) {
#pragma unroll
        for (int o = 16; o; o >>= 1)
            acc[d] += __shfl_xor_sync(0xffffffffu, acc[d], o);
    }

    if (lane == 0) {
        const float t = 2.0f * xi_t;
        float coef = 1.0f;
        float* Mo = Mo_part + (c * ND * B_SIZE + b) * NSPL + sp;
#pragma unroll
        for (int d = 0; d < ND; ++d) {
            if (d > 0) coef *= t * (1.0f / (float)d);   // 1/d is a compile-time constant
            Mo[d * B_SIZE * NSPL] = acc[d] * coef;
        }
    }
}

// Output (R11-proven config): 512 threads = 4 batch-groups x 128 m, grid = (32, 16) = 512 CTAs.
// Preamble: 8 contiguous float4 LDGs per sMo element (32 splits). Channel 15 = raw density.
__global__ __launch_bounds__(512) void output_kernel(const float* __restrict__ xi,
                                                     const float* __restrict__ grid,
                                                     const float* __restrict__ density,
                                                     float* __restrict__ out) {
    const int c = blockIdx.y;
    const int tid = threadIdx.x;
    const int bg = tid >> 7;          // 0..3 -> batches 4*bg..4*bg+3
    const int m = blockIdx.x * 128 + (tid & 127);

    if (c == NCH) {   // raw density channel
#pragma unroll
        for (int q = 0; q < 4; ++q) {
            int b = 4 * bg + q;
            out[(b * 16 + NCH) * G_SIZE + m] = density[b * G_SIZE + m];
        }
        return;
    }

    __shared__ __align__(16) float sMo[ND * B_SIZE];   // 336 floats
    if (tid < ND * B_SIZE) {
        const float4* src = (const float4*)Mo_part + (c * ND * B_SIZE + tid) * (NSPL / 4);
        float s = 0.f;
#pragma unroll
        for (int q = 0; q < NSPL / 4; ++q) {           // 8 contiguous float4 loads
            float4 v = src[q];
            s += (v.x + v.y) + (v.z + v.w);
        }
        sMo[tid] = s;
    }
    __syncthreads();

    float gm = grid[m];
    float xi_t = 1.0f + ex2f(-xi[c] * LOG2E);
    float scale = 0.5f * xi_t * ex2f(-gm * gm * xi_t * LOG2E);

    // 4 independent Horner chains; one broadcast LDS.128 per degree step.
    const float4* col = (const float4*)(sMo) + bg;     // row d -> col[d*4]
    float4 w = col[D_MAX * 4];
    float a0 = w.x, a1 = w.y, a2 = w.z, a3 = w.w;
#pragma unroll
    for (int d = D_MAX - 1; d >= 0; --d) {
        float4 v = col[d * 4];
        a0 = a0 * gm + v.x;
        a1 = a1 * gm + v.y;
        a2 = a2 * gm + v.z;
        a3 = a3 * gm + v.w;
    }

    const int b0 = 4 * bg;
    out[((b0 + 0) * 16 + c) * G_SIZE + m] = a0 * scale;
    out[((b0 + 1) * 16 + c) * G_SIZE + m] = a1 * scale;
    out[((b0 + 2) * 16 + c) * G_SIZE + m] = a2 * scale;
    out[((b0 + 3) * 16 + c) * G_SIZE + m] = a3 * scale;
}

extern "C" void kernel_launch(void* const* d_in, const int* in_sizes, int n_in,
                              void* d_out, int out_size) {
    const float* density = (const float*)d_in[0];  // (16,1,4096)
    const float* xi      = (const float*)d_in[1];  // (15,)
    const float* grid    = (const float*)d_in[2];  // (4096,)
    const float* gw      = (const float*)d_in[3];  // (4096,)
    float* out = (float*)d_out;                    // (16,16,4096)

    moments_kernel<<<dim3(NSPL, NCH), 512>>>(xi, grid, gw, density);
    output_kernel<<<dim3(G_SIZE / 128, NCH + 1), 512>>>(xi, grid, density, out);
}

// round 15
// speedup vs baseline: 1.2548x; 1.2548x over previous
#include <cuda_runtime.h>
#include <cuda_bf16.h>

#define G_SIZE 4096
#define B_SIZE 16
#define NCH 15
#define D_MAX 20          // Taylor degree: terms d = 0..20
#define ND (D_MAX + 1)    // 21
#define NDG (ND / 3)      // 7 degree-groups of 3
#define NSPL 8
#define LPER (G_SIZE / NSPL)   // 512

// Split-innermost layout: Mo_part[((c*ND + d)*B_SIZE + b)*NSPL + sp]
__device__ float Mo_part[NCH * ND * B_SIZE * NSPL];

#define LOG2E 1.4426950408889634f

__device__ __forceinline__ float ex2f(float x) {
    float r; asm("ex2.approx.ftz.f32 %0, %1;" : "=f"(r) : "f"(x)); return r;
}

// gl^e by binary exponentiation (e uniform across CTA -> no divergence)
__device__ __forceinline__ float powu(float g, int e) {
    float p = 1.0f, b = g;
#pragma unroll
    for (int k = 0; k < 5; ++k) {            // e <= 20 < 32
        if (e & 1) p *= b;
        b *= b;
        e >>= 1;
    }
    return p;
}

// Moments partials (R11-proven inner config; NSPL=8 for latency hiding).
// grid = (7 degree-groups, 15 channels, 8 l-splits) = 840 CTAs, 256 threads (8 warps x 2 b)
__global__ __launch_bounds__(256) void moments_kernel(const float* __restrict__ xi,
                                                      const float* __restrict__ grid,
                                                      const float* __restrict__ gw,
                                                      const float* __restrict__ density) {
    __shared__ __align__(16) float prod[3][LPER];      // 6 KB
    const int dg = blockIdx.x;      // 0..6 -> degrees 3dg..3dg+2
    const int c  = blockIdx.y;
    const int sp = blockIdx.z;      // 0..7
    const int tid = threadIdx.x;
    const int l0 = sp * LPER;

    const float xi_t = 1.0f + ex2f(-xi[c] * LOG2E);
    const float cg = -xi_t * LOG2E;
    const int e0 = 3 * dg;

    // Stage: threads 0..127 each build 4 l-entries for all 3 degree rows (float4 path)
    if (tid < LPER / 4) {
        float4 g4 = ((const float4*)(grid + l0))[tid];
        float4 w4 = ((const float4*)(gw + l0))[tid];
        float4 r0, r1, r2;
        {
            float g = g4.x, F = w4.x * ex2f(g * g * cg), p = powu(g, e0);
            r0.x = F * p; p *= g; r1.x = F * p; p *= g; r2.x = F * p;
        }
        {
            float g = g4.y, F = w4.y * ex2f(g * g * cg), p = powu(g, e0);
            r0.y = F * p; p *= g; r1.y = F * p; p *= g; r2.y = F * p;
        }
        {
            float g = g4.z, F = w4.z * ex2f(g * g * cg), p = powu(g, e0);
            r0.z = F * p; p *= g; r1.z = F * p; p *= g; r2.z = F * p;
        }
        {
            float g = g4.w, F = w4.w * ex2f(g * g * cg), p = powu(g, e0);
            r0.w = F * p; p *= g; r1.w = F * p; p *= g; r2.w = F * p;
        }
        ((float4*)prod[0])[tid] = r0;
        ((float4*)prod[1])[tid] = r1;
        ((float4*)prod[2])[tid] = r2;
    }
    __syncthreads();

    const int wid = tid >> 5, lane = tid & 31;

    float t = 2.0f * xi_t;
    float coef0 = 1.0f;
    for (int i = 1; i <= e0; ++i) coef0 = coef0 * t / (float)i;
    float coef1 = coef0 * t / (float)(e0 + 1);
    float coef2 = coef1 * t / (float)(e0 + 2);

    const float4* p0 = (const float4*)prod[0];
    const float4* p1 = (const float4*)prod[1];
    const float4* p2 = (const float4*)prod[2];

#pragma unroll
    for (int bb = 0; bb < 2; ++bb) {
        int b = 2 * wid + bb;
        const float4* dr = (const float4*)(density + b * G_SIZE + l0);
        float s0 = 0.f, s1 = 0.f, s2 = 0.f;
        float u0 = 0.f, u1 = 0.f, u2 = 0.f;
#pragma unroll
        for (int i = 0; i < LPER / 4 / 32; ++i) {      // 4 iters, fully unrolled
            int ix = lane + i * 32;
            float4 d4 = dr[ix];
            float4 a0 = p0[ix], a1 = p1[ix], a2 = p2[ix];
            s0 += d4.x * a0.x + d4.y * a0.y;
            u0 += d4.z * a0.z + d4.w * a0.w;
            s1 += d4.x * a1.x + d4.y * a1.y;
            u1 += d4.z * a1.z + d4.w * a1.w;
            s2 += d4.x * a2.x + d4.y * a2.y;
            u2 += d4.z * a2.z + d4.w * a2.w;
        }
        s0 += u0; s1 += u1; s2 += u2;
#pragma unroll
        for (int o = 16; o; o >>= 1) {
            s0 += __shfl_xor_sync(0xffffffffu, s0, o);
            s1 += __shfl_xor_sync(0xffffffffu, s1, o);
            s2 += __shfl_xor_sync(0xffffffffu, s2, o);
        }
        if (lane == 0) {
            Mo_part[((c * ND + e0 + 0) * B_SIZE + b) * NSPL + sp] = s0 * coef0;
            Mo_part[((c * ND + e0 + 1) * B_SIZE + b) * NSPL + sp] = s1 * coef1;
            Mo_part[((c * ND + e0 + 2) * B_SIZE + b) * NSPL + sp] = s2 * coef2;
        }
    }
}

// Output (R11 geometry: 512 threads = 4 batch-groups x 128 m, grid (32,16) = 512 CTAs),
// with a depth-3 software pipeline on the Horner coefficient LDS loads.
__global__ __launch_bounds__(512) void output_kernel(const float* __restrict__ xi,
                                                     const float* __restrict__ grid,
                                                     const float* __restrict__ density,
                                                     float* __restrict__ out) {
    const int c = blockIdx.y;
    const int tid = threadIdx.x;
    const int bg = tid >> 7;          // 0..3 -> batches 4*bg..4*bg+3
    const int m = blockIdx.x * 128 + (tid & 127);

    if (c == NCH) {   // raw density channel
#pragma unroll
        for (int q = 0; q < 4; ++q) {
            int b = 4 * bg + q;
            out[(b * 16 + NCH) * G_SIZE + m] = density[b * G_SIZE + m];
        }
        return;
    }

    __shared__ __align__(16) float sMo[ND * B_SIZE];   // 336 floats
    if (tid < ND * B_SIZE) {
        const float4* src = (const float4*)Mo_part + (c * ND * B_SIZE + tid) * (NSPL / 4);
        float4 v0 = src[0];
        float4 v1 = src[1];
        sMo[tid] = ((v0.x + v0.y) + (v0.z + v0.w)) + ((v1.x + v1.y) + (v1.z + v1.w));
    }
    __syncthreads();

    float gm = grid[m];
    float xi_t = 1.0f + ex2f(-xi[c] * LOG2E);
    float scale = 0.5f * xi_t * ex2f(-gm * gm * xi_t * LOG2E);

    // 4 independent Horner chains; coefficient LDS.128s prefetched 3 steps ahead.
    const float4* col = (const float4*)(sMo) + bg;     // row d -> col[d*4]
    float4 w = col[D_MAX * 4];
    float a0 = w.x, a1 = w.y, a2 = w.z, a3 = w.w;
    float4 f0 = col[(D_MAX - 1) * 4];
    float4 f1 = col[(D_MAX - 2) * 4];
    float4 f2 = col[(D_MAX - 3) * 4];
#pragma unroll
    for (int d = D_MAX - 1; d >= 0; --d) {
        float4 v = f0;
        f0 = f1;
        f1 = f2;
        if (d >= 3) f2 = col[(d - 3) * 4];             // compile-time guard (full unroll)
        a0 = a0 * gm + v.x;
        a1 = a1 * gm + v.y;
        a2 = a2 * gm + v.z;
        a3 = a3 * gm + v.w;
    }

    const int b0 = 4 * bg;
    out[((b0 + 0) * 16 + c) * G_SIZE + m] = a0 * scale;
    out[((b0 + 1) * 16 + c) * G_SIZE + m] = a1 * scale;
    out[((b0 + 2) * 16 + c) * G_SIZE + m] = a2 * scale;
    out[((b0 + 3) * 16 + c) * G_SIZE + m] = a3 * scale;
}

extern "C" void kernel_launch(void* const* d_in, const int* in_sizes, int n_in,
                              void* d_out, int out_size) {
    const float* density = (const float*)d_in[0];  // (16,1,4096)
    const float* xi      = (const float*)d_in[1];  // (15,)
    const float* grid    = (const float*)d_in[2];  // (4096,)
    const float* gw      = (const float*)d_in[3];  // (4096,)
    float* out = (float*)d_out;                    // (16,16,4096)

    moments_kernel<<<dim3(NDG, NCH, NSPL), 256>>>(xi, grid, gw, density);
    output_kernel<<<dim3(G_SIZE / 128, NCH + 1), 512>>>(xi, grid, density, out);
}

// round 16
// speedup vs baseline: 1.4812x; 1.1805x over previous
#include <cuda_runtime.h>
#include <cuda_bf16.h>

#define G_SIZE 4096
#define B_SIZE 16
#define NCH 15
#define D_MAX 20          // Taylor degree: terms d = 0..20
#define ND (D_MAX + 1)    // 21
#define NDG (ND / 3)      // 7 degree-groups of 3
#define NSPL 4
#define LPER (G_SIZE / NSPL)   // 1024

// Split-innermost layout: Mo_part[((c*ND + d)*B_SIZE + b)*NSPL + sp]
__device__ float Mo_part[NCH * ND * B_SIZE * NSPL];

#define LOG2E 1.4426950408889634f

__device__ __forceinline__ float ex2f(float x) {
    float r; asm("ex2.approx.ftz.f32 %0, %1;" : "=f"(r) : "f"(x)); return r;
}

// gl^e by binary exponentiation (e uniform across CTA -> no divergence)
__device__ __forceinline__ float powu(float g, int e) {
    float p = 1.0f, b = g;
#pragma unroll
    for (int k = 0; k < 5; ++k) {            // e <= 20 < 32
        if (e & 1) p *= b;
        b *= b;
        e >>= 1;
    }
    return p;
}

// Moments partials (R11 geometry; single merged dot pass over both batches).
// grid = (7 degree-groups, 15 channels, 4 l-splits) = 420 CTAs, 256 threads (8 warps x 2 b)
__global__ __launch_bounds__(256) void moments_kernel(const float* __restrict__ xi,
                                                      const float* __restrict__ grid,
                                                      const float* __restrict__ gw,
                                                      const float* __restrict__ density) {
    __shared__ __align__(16) float prod[3][LPER];      // 12 KB
    const int dg = blockIdx.x;      // 0..6 -> degrees 3dg..3dg+2
    const int c  = blockIdx.y;
    const int sp = blockIdx.z;      // 0..3
    const int tid = threadIdx.x;
    const int l0 = sp * LPER;

    const float xi_t = 1.0f + ex2f(-xi[c] * LOG2E);
    const float cg = -xi_t * LOG2E;
    const int e0 = 3 * dg;

    // Stage: each of 256 threads builds 4 l-entries for all 3 degree rows (R11-proven)
    {
        float4 g4 = ((const float4*)(grid + l0))[tid];
        float4 w4 = ((const float4*)(gw + l0))[tid];
        float4 r0, r1, r2;
        {
            float g = g4.x, F = w4.x * ex2f(g * g * cg), p = powu(g, e0);
            r0.x = F * p; p *= g; r1.x = F * p; p *= g; r2.x = F * p;
        }
        {
            float g = g4.y, F = w4.y * ex2f(g * g * cg), p = powu(g, e0);
            r0.y = F * p; p *= g; r1.y = F * p; p *= g; r2.y = F * p;
        }
        {
            float g = g4.z, F = w4.z * ex2f(g * g * cg), p = powu(g, e0);
            r0.z = F * p; p *= g; r1.z = F * p; p *= g; r2.z = F * p;
        }
        {
            float g = g4.w, F = w4.w * ex2f(g * g * cg), p = powu(g, e0);
            r0.w = F * p; p *= g; r1.w = F * p; p *= g; r2.w = F * p;
        }
        ((float4*)prod[0])[tid] = r0;
        ((float4*)prod[1])[tid] = r1;
        ((float4*)prod[2])[tid] = r2;
    }
    __syncthreads();

    const int wid = tid >> 5, lane = tid & 31;

    float t = 2.0f * xi_t;
    float coef0 = 1.0f;
    for (int i = 1; i <= e0; ++i) coef0 = coef0 * t / (float)i;
    float coef1 = coef0 * t / (float)(e0 + 1);
    float coef2 = coef1 * t / (float)(e0 + 2);

    const float4* p0 = (const float4*)prod[0];
    const float4* p1 = (const float4*)prod[1];
    const float4* p2 = (const float4*)prod[2];

    // Merged pass: both batches (2*wid, 2*wid+1) in one loop — prod rows read ONCE,
    // 2x independent LDGs per iteration window, 24 FMAs per 5 memory ops.
    const int ba = 2 * wid, bb2 = 2 * wid + 1;
    const float4* dra = (const float4*)(density + ba * G_SIZE + l0);
    const float4* drb = (const float4*)(density + bb2 * G_SIZE + l0);

    float s0a = 0.f, s1a = 0.f, s2a = 0.f, u0a = 0.f, u1a = 0.f, u2a = 0.f;
    float s0b = 0.f, s1b = 0.f, s2b = 0.f, u0b = 0.f, u1b = 0.f, u2b = 0.f;
#pragma unroll
    for (int i = 0; i < LPER / 4 / 32; ++i) {          // 8 iters, fully unrolled
        int ix = lane + i * 32;
        float4 da = dra[ix];
        float4 db = drb[ix];
        float4 a0 = p0[ix], a1 = p1[ix], a2 = p2[ix];
        s0a += da.x * a0.x + da.y * a0.y;  u0a += da.z * a0.z + da.w * a0.w;
        s1a += da.x * a1.x + da.y * a1.y;  u1a += da.z * a1.z + da.w * a1.w;
        s2a += da.x * a2.x + da.y * a2.y;  u2a += da.z * a2.z + da.w * a2.w;
        s0b += db.x * a0.x + db.y * a0.y;  u0b += db.z * a0.z + db.w * a0.w;
        s1b += db.x * a1.x + db.y * a1.y;  u1b += db.z * a1.z + db.w * a1.w;
        s2b += db.x * a2.x + db.y * a2.y;  u2b += db.z * a2.z + db.w * a2.w;
    }
    s0a += u0a; s1a += u1a; s2a += u2a;
    s0b += u0b; s1b += u1b; s2b += u2b;
#pragma unroll
    for (int o = 16; o; o >>= 1) {
        s0a += __shfl_xor_sync(0xffffffffu, s0a, o);
        s1a += __shfl_xor_sync(0xffffffffu, s1a, o);
        s2a += __shfl_xor_sync(0xffffffffu, s2a, o);
        s0b += __shfl_xor_sync(0xffffffffu, s0b, o);
        s1b += __shfl_xor_sync(0xffffffffu, s1b, o);
        s2b += __shfl_xor_sync(0xffffffffu, s2b, o);
    }
    if (lane == 0) {
        Mo_part[((c * ND + e0 + 0) * B_SIZE + ba) * NSPL + sp] = s0a * coef0;
        Mo_part[((c * ND + e0 + 1) * B_SIZE + ba) * NSPL + sp] = s1a * coef1;
        Mo_part[((c * ND + e0 + 2) * B_SIZE + ba) * NSPL + sp] = s2a * coef2;
        Mo_part[((c * ND + e0 + 0) * B_SIZE + bb2) * NSPL + sp] = s0b * coef0;
        Mo_part[((c * ND + e0 + 1) * B_SIZE + bb2) * NSPL + sp] = s1b * coef1;
        Mo_part[((c * ND + e0 + 2) * B_SIZE + bb2) * NSPL + sp] = s2b * coef2;
    }
}

// Output (R11-proven, byte-identical): 512 threads = 4 batch-groups x 128 m,
// grid = (32 m-blocks, 16 channels) = 512 CTAs. Channel 15 = raw density.
__global__ __launch_bounds__(512) void output_kernel(const float* __restrict__ xi,
                                                     const float* __restrict__ grid,
                                                     const float* __restrict__ density,
                                                     float* __restrict__ out) {
    const int c = blockIdx.y;
    const int tid = threadIdx.x;
    const int bg = tid >> 7;          // 0..3 -> batches 4*bg..4*bg+3
    const int m = blockIdx.x * 128 + (tid & 127);

    if (c == NCH) {   // raw density channel
#pragma unroll
        for (int q = 0; q < 4; ++q) {
            int b = 4 * bg + q;
            out[(b * 16 + NCH) * G_SIZE + m] = density[b * G_SIZE + m];
        }
        return;
    }

    __shared__ __align__(16) float sMo[ND * B_SIZE];   // 336 floats
    if (tid < ND * B_SIZE) {
        float4 v = ((const float4*)Mo_part)[c * ND * B_SIZE + tid];
        sMo[tid] = (v.x + v.y) + (v.z + v.w);
    }
    __syncthreads();

    float gm = grid[m];
    float xi_t = 1.0f + ex2f(-xi[c] * LOG2E);
    float scale = 0.5f * xi_t * ex2f(-gm * gm * xi_t * LOG2E);

    // 4 independent Horner chains; one broadcast LDS.128 per degree step.
    const float4* col = (const float4*)(sMo) + bg;     // row d -> col[d*4]
    float4 w = col[D_MAX * 4];
    float a0 = w.x, a1 = w.y, a2 = w.z, a3 = w.w;
#pragma unroll
    for (int d = D_MAX - 1; d >= 0; --d) {
        float4 v = col[d * 4];
        a0 = a0 * gm + v.x;
        a1 = a1 * gm + v.y;
        a2 = a2 * gm + v.z;
        a3 = a3 * gm + v.w;
    }

    const int b0 = 4 * bg;
    out[((b0 + 0) * 16 + c) * G_SIZE + m] = a0 * scale;
    out[((b0 + 1) * 16 + c) * G_SIZE + m] = a1 * scale;
    out[((b0 + 2) * 16 + c) * G_SIZE + m] = a2 * scale;
    out[((b0 + 3) * 16 + c) * G_SIZE + m] = a3 * scale;
}

extern "C" void kernel_launch(void* const* d_in, const int* in_sizes, int n_in,
                              void* d_out, int out_size) {
    const float* density = (const float*)d_in[0];  // (16,1,4096)
    const float* xi      = (const float*)d_in[1];  // (15,)
    const float* grid    = (const float*)d_in[2];  // (4096,)
    const float* gw      = (const float*)d_in[3];  // (4096,)
    float* out = (float*)d_out;                    // (16,16,4096)

    moments_kernel<<<dim3(NDG, NCH, NSPL), 256>>>(xi, grid, gw, density);
    output_kernel<<<dim3(G_SIZE / 128, NCH + 1), 512>>>(xi, grid, density, out);
}